// round 4
// baseline (speedup 1.0000x reference)
#include <cuda_runtime.h>
#include <cstdint>

// Problem constants
#define B_    4096
#define NM_   25
#define C_    64
#define NNZ_  1000
#define NW_   55
#define NNZP_ 1024          // padded (8 warps x 128 entries)
#define EPW_  128           // entries per warp
#define NBIN  625           // mo*25 + m1
#define NBINP 640

#define THR   256           // 8 warps/CTA, 1 batch/CTA
#define GRID  B_

// Reordered tables (batch-independent), rebuilt by prep every launch.
__device__ unsigned g_pk[2 * NNZP_];   // per entry: A = o1|o2<<16, B = ol|flag<<15|om<<16 (o* = idx*256)
__device__ float    g_cg[NNZP_];

// ---------------- prep: counting-sort entries by (mo,m1), pre-shift offsets, set load-a flags ----------------
__global__ __launch_bounds__(1024, 1)
void prep_kernel(const float* __restrict__ cg,
                 const int* __restrict__ Mo,  const int* __restrict__ M1,
                 const int* __restrict__ M2,  const int* __restrict__ Li)
{
    __shared__ int      hist[NBINP];
    __shared__ int      keys[NNZ_];
    __shared__ unsigned sA[NNZP_], sB[NNZP_];
    __shared__ float    sC[NNZP_];
    __shared__ short    skey[NNZP_];
    __shared__ int      wsum[32];

    const int tid  = threadIdx.x;
    const int lane = tid & 31;
    const int wrp  = tid >> 5;

    if (tid < NBINP) hist[tid] = 0;
    __syncthreads();

    int key = 0;
    if (tid < NNZ_) {
        key = Mo[tid] * 25 + M1[tid];
        keys[tid] = key;
        atomicAdd(&hist[key], 1);
    }
    __syncthreads();

    // exclusive scan over 640 bins: 20 warps x 32, then warp-0 combines
    if (wrp < 20) {
        int bin = wrp * 32 + lane;
        int v = hist[bin];
        int inc = v;
        #pragma unroll
        for (int d = 1; d < 32; d <<= 1) {
            int t = __shfl_up_sync(0xFFFFFFFFu, inc, d);
            if (lane >= d) inc += t;
        }
        if (lane == 31) wsum[wrp] = inc;
        hist[bin] = inc - v;           // exclusive within warp
    }
    __syncthreads();
    if (wrp == 0) {
        int v = (lane < 20) ? wsum[lane] : 0;
        int inc = v;
        #pragma unroll
        for (int d = 1; d < 32; d <<= 1) {
            int t = __shfl_up_sync(0xFFFFFFFFu, inc, d);
            if (lane >= d) inc += t;
        }
        if (lane < 20) wsum[lane] = inc - v;   // exclusive warp base
    }
    __syncthreads();
    if (wrp < 20) hist[wrp * 32 + lane] += wsum[wrp];
    __syncthreads();

    // scatter (order within a (mo,m1) bin is arbitrary: sum reassociation only)
    if (tid < NNZ_) {
        int idx = atomicAdd(&hist[key], 1);
        unsigned o1 = (unsigned)M1[tid] << 8;
        unsigned o2 = (unsigned)M2[tid] << 8;
        unsigned ol = (unsigned)Li[tid] << 8;
        unsigned om = (unsigned)Mo[tid] << 8;
        sA[idx] = o1 | (o2 << 16);
        sB[idx] = ol | (om << 16);
        sC[idx] = cg[tid];
        skey[idx] = (short)key;
    }
    __syncthreads();

    // pads + load-a flags + writeout
    if (tid < NNZP_) {
        unsigned A, Bw; float Cv;
        if (tid < NNZ_) {
            A = sA[tid]; Bw = sB[tid]; Cv = sC[tid];
            int f = (tid == 0) || ((tid & (EPW_ - 1)) == 0) || (skey[tid] != skey[tid - 1]);
            if (f) Bw |= 0x8000u;
        } else {
            A = 0; Bw = sB[NNZ_ - 1] & 0xFFFF0000u; Cv = 0.f;  // cg=0 dummy, same mo as last
        }
        g_pk[2 * tid]     = A;
        g_pk[2 * tid + 1] = Bw;
        g_cg[tid]         = Cv;
    }
}

// ---------------- main kernel ----------------
// SMEM: x1 (1600) + x2 (1600) + w (3520) floats = 26880 B
#define SM_X1 0
#define SM_X2 (SM_X1 + NM_*C_)
#define SM_W  (SM_X2 + NM_*C_)
#define SM_FLOATS (SM_W + NW_*C_)
#define SM_BYTES  (SM_FLOATS * 4)

__global__ __launch_bounds__(THR, 6)
void wtp_kernel(const float* __restrict__ x1,
                const float* __restrict__ x2,
                const float* __restrict__ wgt,
                float* __restrict__ out)
{
    extern __shared__ float smem[];
    float* s_x1 = smem + SM_X1;
    float* s_x2 = smem + SM_X2;
    float* s_w  = smem + SM_W;

    const int tid  = threadIdx.x;
    const int lane = tid & 31;
    const int wrp  = tid >> 5;
    const int b    = blockIdx.x;

    // stage this batch's operands (coalesced float4)
    {
        const float4* g1 = (const float4*)(x1 + (size_t)b * NM_ * C_);
        const float4* g2 = (const float4*)(x2 + (size_t)b * NM_ * C_);
        const float4* gw = (const float4*)(wgt + (size_t)b * NW_ * C_);
        float4* d1 = (float4*)s_x1;
        float4* d2 = (float4*)s_x2;
        float4* dw = (float4*)s_w;
        #pragma unroll 2
        for (int i = tid; i < NM_*C_/4; i += THR) { d1[i] = g1[i]; d2[i] = g2[i]; }
        #pragma unroll 4
        for (int i = tid; i < NW_*C_/4; i += THR) { dw[i] = gw[i]; }
    }
    __syncthreads();

    // per-warp: 128 reordered entries; lanes = float2 channel pairs (byte offsets)
    const char* p1 = (const char*)s_x1 + lane * 8;
    const char* p2 = (const char*)s_x2 + lane * 8;
    const char* pw = (const char*)s_w  + lane * 8;
    char* ob = (char*)(out + (size_t)b * NM_ * C_) + lane * 8;

    const int e0 = wrp * EPW_;
    const uint4*  tp = (const uint4*)(g_pk + 2 * e0);   // 2 entries per uint4
    const float4* tc = (const float4*)(g_cg + e0);

    float ax = 0.f, ay = 0.f;
    float2 a_ = make_float2(0.f, 0.f);                  // first entry of warp always has flag set
    unsigned cur = g_pk[2 * e0 + 1] >> 16;              // mo*256 of first entry
    int first = 1;

    #define STEP(A, Bw, CGV) do {                                        \
        unsigned o1_ = (A) & 0xFFFFu;                                    \
        unsigned o2_ = (A) >> 16;                                        \
        unsigned ol_ = (Bw) & 0x3FFFu;                                   \
        unsigned om_ = (Bw) >> 16;                                       \
        if (om_ != cur) {  /* warp-uniform, rarely taken */              \
            float* dst_ = (float*)(ob + cur);                            \
            if (first) { atomicAdd(dst_, ax); atomicAdd(dst_+1, ay); first = 0; } \
            else       { *(float2*)dst_ = make_float2(ax, ay); }         \
            ax = 0.f; ay = 0.f; cur = om_;                               \
        }                                                                \
        if ((Bw) & 0x8000u) a_ = *(const float2*)(p1 + o1_);             \
        float2 b_ = *(const float2*)(p2 + o2_);                          \
        float2 w_ = *(const float2*)(pw + ol_);                          \
        ax = fmaf(a_.x * b_.x, (CGV) * w_.x, ax);                        \
        ay = fmaf(a_.y * b_.y, (CGV) * w_.y, ay);                        \
    } while (0)

    #pragma unroll 4
    for (int q = 0; q < EPW_ / 4; ++q) {
        uint4  u0 = tp[2*q];      // entries 4q, 4q+1
        uint4  u1 = tp[2*q + 1];  // entries 4q+2, 4q+3
        float4 c4 = tc[q];
        STEP(u0.x, u0.y, c4.x);
        STEP(u0.z, u0.w, c4.y);
        STEP(u1.x, u1.y, c4.z);
        STEP(u1.z, u1.w, c4.w);
    }
    // final segment may straddle next warp -> atomic
    {
        float* dst = (float*)(ob + cur);
        atomicAdd(dst,     ax);
        atomicAdd(dst + 1, ay);
    }
}

extern "C" void kernel_launch(void* const* d_in, const int* in_sizes, int n_in,
                              void* d_out, int out_size)
{
    const float* x1  = (const float*)d_in[0];
    const float* x2  = (const float*)d_in[1];
    const float* wgt = (const float*)d_in[2];
    const float* cg  = (const float*)d_in[3];
    const int*   Mo  = (const int*)d_in[4];
    const int*   M1  = (const int*)d_in[5];
    const int*   M2  = (const int*)d_in[6];
    const int*   Li  = (const int*)d_in[7];
    float* out = (float*)d_out;

    cudaMemsetAsync(d_out, 0, (size_t)out_size * sizeof(float), 0);
    prep_kernel<<<1, 1024>>>(cg, Mo, M1, M2, Li);
    cudaFuncSetAttribute(wtp_kernel, cudaFuncAttributeMaxDynamicSharedMemorySize, SM_BYTES);
    wtp_kernel<<<GRID, THR, SM_BYTES>>>(x1, x2, wgt, out);
}

// round 5
// speedup vs baseline: 1.1538x; 1.1538x over previous
#include <cuda_runtime.h>
#include <cstdint>

// Problem constants
#define B_    4096
#define NM_   25
#define C_    64
#define NNZ_  1000
#define NW_   55
#define NNZP_ 1024          // padded (8 warps x 128 entries)
#define EPW_  128
#define NBINP 640

#define THR   512           // 16 warps: warps 0-7 -> batch0, 8-15 -> batch1
#define BPB   2
#define GRID  (B_ / BPB)    // 2048

// Reordered tables (batch-independent), rebuilt by prep every launch.
// layout: [0 .. 2*NNZP_) : per entry {A = o1|o2<<16 , B = ol|flag<<15|om<<16} interleaved
//         [2*NNZP_ .. 3*NNZP_) : cg (float bits)
__device__ unsigned g_tab[3 * NNZP_];

// ---------------- prep: counting-sort by (mo,m1), pre-shift to byte offsets, set load-a flags ----------------
__global__ __launch_bounds__(1024, 1)
void prep_kernel(const float* __restrict__ cg,
                 const int* __restrict__ Mo,  const int* __restrict__ M1,
                 const int* __restrict__ M2,  const int* __restrict__ Li)
{
    __shared__ int      hist[NBINP];
    __shared__ unsigned sA[NNZP_], sB[NNZP_];
    __shared__ float    sC[NNZP_];
    __shared__ short    skey[NNZP_];
    __shared__ int      wsum[32];

    const int tid  = threadIdx.x;
    const int lane = tid & 31;
    const int wrp  = tid >> 5;

    if (tid < NBINP) hist[tid] = 0;
    __syncthreads();

    int key = 0;
    if (tid < NNZ_) {
        key = Mo[tid] * 25 + M1[tid];
        atomicAdd(&hist[key], 1);
    }
    __syncthreads();

    // exclusive scan over 640 bins
    if (wrp < 20) {
        int bin = wrp * 32 + lane;
        int v = hist[bin];
        int inc = v;
        #pragma unroll
        for (int d = 1; d < 32; d <<= 1) {
            int t = __shfl_up_sync(0xFFFFFFFFu, inc, d);
            if (lane >= d) inc += t;
        }
        if (lane == 31) wsum[wrp] = inc;
        hist[bin] = inc - v;
    }
    __syncthreads();
    if (wrp == 0) {
        int v = (lane < 20) ? wsum[lane] : 0;
        int inc = v;
        #pragma unroll
        for (int d = 1; d < 32; d <<= 1) {
            int t = __shfl_up_sync(0xFFFFFFFFu, inc, d);
            if (lane >= d) inc += t;
        }
        if (lane < 20) wsum[lane] = inc - v;
    }
    __syncthreads();
    if (wrp < 20) hist[wrp * 32 + lane] += wsum[wrp];
    __syncthreads();

    // scatter (order within a (mo,m1) bin arbitrary: sum reassociation only)
    if (tid < NNZ_) {
        int idx = atomicAdd(&hist[key], 1);
        sA[idx] = ((unsigned)M1[tid] << 8) | ((unsigned)M2[tid] << 24);
        sB[idx] = ((unsigned)Li[tid] << 8) | ((unsigned)Mo[tid] << 24);
        sC[idx] = cg[tid];
        skey[idx] = (short)key;
    }
    __syncthreads();

    // pads + load-a flags + writeout
    if (tid < NNZP_) {
        unsigned A, Bw; float Cv;
        if (tid < NNZ_) {
            A = sA[tid]; Bw = sB[tid]; Cv = sC[tid];
            int f = (tid == 0) || ((tid & (EPW_ - 1)) == 0) || (skey[tid] != skey[tid - 1]);
            if (f) Bw |= 0x8000u;
        } else {
            A = 0; Bw = sB[NNZ_ - 1] & 0xFFFF0000u; Cv = 0.f;  // cg=0 dummy, same mo as last
        }
        g_tab[2 * tid]       = A;
        g_tab[2 * tid + 1]   = Bw;
        g_tab[2 * NNZP_ + tid] = __float_as_uint(Cv);
    }
}

// ---------------- main kernel ----------------
// SMEM (floats): 2 x [x1(1600) x2(1600) w(3520)] = 13440, then tables (3*1024 words)
#define SMB_   (2*NM_*C_ + NW_*C_)        // 6720 floats per batch
#define SM_PK  (2 * SMB_)                 // 13440 (16B-aligned: 53760 B)
#define SM_CG  (SM_PK + 2 * NNZP_)
#define SM_FLOATS (SM_CG + NNZP_)         // 16512
#define SM_BYTES  (SM_FLOATS * 4)         // 66048

__global__ __launch_bounds__(THR, 3)
void wtp_kernel(const float* __restrict__ x1,
                const float* __restrict__ x2,
                const float* __restrict__ wgt,
                float* __restrict__ out)
{
    extern __shared__ float smem[];
    const int tid  = threadIdx.x;
    const int lane = tid & 31;
    const int wrp  = tid >> 5;

    // ---- stage: threads 0-255 -> batch0, 256-511 -> batch1 (coalesced float4) ----
    {
        const int half = tid >> 8;
        const int tl   = tid & 255;
        const int b    = blockIdx.x * BPB + half;
        float* sb = smem + half * SMB_;
        const float4* g1 = (const float4*)(x1 + (size_t)b * NM_ * C_);
        const float4* g2 = (const float4*)(x2 + (size_t)b * NM_ * C_);
        const float4* gw = (const float4*)(wgt + (size_t)b * NW_ * C_);
        float4* d1 = (float4*)sb;
        float4* d2 = (float4*)(sb + NM_ * C_);
        float4* dw = (float4*)(sb + 2 * NM_ * C_);
        #pragma unroll 2
        for (int i = tl; i < NM_*C_/4; i += 256) { d1[i] = g1[i]; d2[i] = g2[i]; }
        #pragma unroll 4
        for (int i = tl; i < NW_*C_/4; i += 256) { dw[i] = gw[i]; }
        // tables: 3072 words = 768 uint4, all 512 threads
        const uint4* gt = (const uint4*)g_tab;
        uint4* dt = (uint4*)(smem + SM_PK);
        #pragma unroll 2
        for (int i = tid; i < 3 * NNZP_ / 4; i += THR) dt[i] = gt[i];
    }
    __syncthreads();

    // ---- per-warp: 128 reordered entries of this warp-group's batch ----
    const int half = wrp >> 3;
    const int b    = blockIdx.x * BPB + half;
    const float* sb = smem + half * SMB_;
    const char* p1 = (const char*)sb + lane * 8;
    const char* p2 = (const char*)(sb + NM_ * C_) + lane * 8;
    const char* pw = (const char*)(sb + 2 * NM_ * C_) + lane * 8;
    char* ob = (char*)(out + (size_t)b * NM_ * C_) + lane * 8;

    const unsigned* s_pk = (const unsigned*)(smem + SM_PK);
    const float*    s_cg = smem + SM_CG;

    const int e0 = (wrp & 7) * EPW_;
    const uint4*  tp = (const uint4*)(s_pk + 2 * e0);   // 2 entries per uint4 (LDS.128 broadcast)
    const float4* tc = (const float4*)(s_cg + e0);

    float ax = 0.f, ay = 0.f;
    float2 a_ = make_float2(0.f, 0.f);                  // first entry of warp always flagged
    unsigned cur = s_pk[2 * e0 + 1] >> 16;              // mo*256 of first entry
    int first = 1;

    #define STEP(A, Bw, CGV) do {                                        \
        unsigned o1_ = (A) & 0xFFFFu;                                    \
        unsigned o2_ = (A) >> 16;                                        \
        unsigned ol_ = (Bw) & 0x3FFFu;                                   \
        unsigned om_ = (Bw) >> 16;                                       \
        if (om_ != cur) {  /* warp-uniform, rarely taken */              \
            float* dst_ = (float*)(ob + cur);                            \
            if (first) { atomicAdd(dst_, ax); atomicAdd(dst_+1, ay); first = 0; } \
            else       { *(float2*)dst_ = make_float2(ax, ay); }         \
            ax = 0.f; ay = 0.f; cur = om_;                               \
        }                                                                \
        if ((Bw) & 0x8000u) a_ = *(const float2*)(p1 + o1_);             \
        float2 b_ = *(const float2*)(p2 + o2_);                          \
        float2 w_ = *(const float2*)(pw + ol_);                          \
        ax = fmaf(a_.x * b_.x, (CGV) * w_.x, ax);                        \
        ay = fmaf(a_.y * b_.y, (CGV) * w_.y, ay);                        \
    } while (0)

    #pragma unroll 4
    for (int q = 0; q < EPW_ / 4; ++q) {
        uint4  u0 = tp[2*q];
        uint4  u1 = tp[2*q + 1];
        float4 c4 = tc[q];
        STEP(u0.x, u0.y, c4.x);
        STEP(u0.z, u0.w, c4.y);
        STEP(u1.x, u1.y, c4.z);
        STEP(u1.z, u1.w, c4.w);
    }
    // final segment may straddle next warp -> atomic
    {
        float* dst = (float*)(ob + cur);
        atomicAdd(dst,     ax);
        atomicAdd(dst + 1, ay);
    }
}

extern "C" void kernel_launch(void* const* d_in, const int* in_sizes, int n_in,
                              void* d_out, int out_size)
{
    const float* x1  = (const float*)d_in[0];
    const float* x2  = (const float*)d_in[1];
    const float* wgt = (const float*)d_in[2];
    const float* cg  = (const float*)d_in[3];
    const int*   Mo  = (const int*)d_in[4];
    const int*   M1  = (const int*)d_in[5];
    const int*   M2  = (const int*)d_in[6];
    const int*   Li  = (const int*)d_in[7];
    float* out = (float*)d_out;

    cudaMemsetAsync(d_out, 0, (size_t)out_size * sizeof(float), 0);
    prep_kernel<<<1, 1024>>>(cg, Mo, M1, M2, Li);
    cudaFuncSetAttribute(wtp_kernel, cudaFuncAttributeMaxDynamicSharedMemorySize, SM_BYTES);
    wtp_kernel<<<GRID, THR, SM_BYTES>>>(x1, x2, wgt, out);
}

// round 8
// speedup vs baseline: 1.2886x; 1.1168x over previous
#include <cuda_runtime.h>
#include <cstdint>

// Problem constants
#define B_    4096
#define NM_   25
#define C_    64
#define NNZ_  1000
#define NW_   55
#define NNZP_ 1024          // padded (16 warps x 64 entries)
#define EPW_  64            // entries per warp slice
#define NBINP 640

#define THR   512           // 16 warps; each warp: 64-entry slice x BOTH batches
#define BPB   2
#define GRID  (B_ / BPB)    // 2048

// Reordered tables (batch-independent), rebuilt by prep every launch.
// layout (words): [0 .. 2*NNZP_): per entry {A = o1|o2<<16, B = ol|flag<<15|om<<16}
//                 [2*NNZP_ .. 3*NNZP_): cg bits
__device__ unsigned g_tab[3 * NNZP_];

// ---------------- prep: counting-sort by (mo,m1), pre-shift to byte offsets, set load-a flags ----------------
__global__ __launch_bounds__(1024, 1)
void prep_kernel(const float* __restrict__ cg,
                 const int* __restrict__ Mo,  const int* __restrict__ M1,
                 const int* __restrict__ M2,  const int* __restrict__ Li)
{
    __shared__ int      hist[NBINP];
    __shared__ unsigned sA[NNZP_], sB[NNZP_];
    __shared__ float    sC[NNZP_];
    __shared__ short    skey[NNZP_];
    __shared__ int      wsum[32];

    const int tid  = threadIdx.x;
    const int lane = tid & 31;
    const int wrp  = tid >> 5;

    if (tid < NBINP) hist[tid] = 0;
    __syncthreads();

    int key = 0;
    if (tid < NNZ_) {
        key = Mo[tid] * 25 + M1[tid];
        atomicAdd(&hist[key], 1);
    }
    __syncthreads();

    // exclusive scan over 640 bins
    if (wrp < 20) {
        int bin = wrp * 32 + lane;
        int v = hist[bin];
        int inc = v;
        #pragma unroll
        for (int d = 1; d < 32; d <<= 1) {
            int t = __shfl_up_sync(0xFFFFFFFFu, inc, d);
            if (lane >= d) inc += t;
        }
        if (lane == 31) wsum[wrp] = inc;
        hist[bin] = inc - v;
    }
    __syncthreads();
    if (wrp == 0) {
        int v = (lane < 20) ? wsum[lane] : 0;
        int inc = v;
        #pragma unroll
        for (int d = 1; d < 32; d <<= 1) {
            int t = __shfl_up_sync(0xFFFFFFFFu, inc, d);
            if (lane >= d) inc += t;
        }
        if (lane < 20) wsum[lane] = inc - v;
    }
    __syncthreads();
    if (wrp < 20) hist[wrp * 32 + lane] += wsum[wrp];
    __syncthreads();

    // scatter (order within a (mo,m1) bin arbitrary: sum reassociation only)
    if (tid < NNZ_) {
        int idx = atomicAdd(&hist[key], 1);
        sA[idx] = ((unsigned)M1[tid] << 8) | ((unsigned)M2[tid] << 24);
        sB[idx] = ((unsigned)Li[tid] << 8) | ((unsigned)Mo[tid] << 24);
        sC[idx] = cg[tid];
        skey[idx] = (short)key;
    }
    __syncthreads();

    // pads + load-a flags (slice boundary now every EPW_=64 entries) + writeout
    if (tid < NNZP_) {
        unsigned A, Bw; float Cv;
        if (tid < NNZ_) {
            A = sA[tid]; Bw = sB[tid]; Cv = sC[tid];
            int f = (tid == 0) || ((tid & (EPW_ - 1)) == 0) || (skey[tid] != skey[tid - 1]);
            if (f) Bw |= 0x8000u;
        } else {
            A = 0; Bw = sB[NNZ_ - 1] & 0xFFFF0000u; Cv = 0.f;  // cg=0 dummy, same mo as last
        }
        g_tab[2 * tid]         = A;
        g_tab[2 * tid + 1]     = Bw;
        g_tab[2 * NNZP_ + tid] = __float_as_uint(Cv);
    }
}

// ---------------- main kernel ----------------
// SMEM (floats): 2 x [x1(1600) x2(1600) w(3520)] = 13440, then pk (2048 w) + cg (1024 w)
#define SMB_      (2*NM_*C_ + NW_*C_)     // 6720 floats per batch
#define B1OFF     (SMB_ * 4)              // 26880 B: batch1 operand offset in SMEM
#define X2OFF     (NM_*C_*4)              // 6400 B
#define WOFF      (2*NM_*C_*4)            // 12800 B
#define OB1       (NM_*C_*4)              // 6400 B: batch1 offset in out
#define SM_PK     (2 * SMB_)              // 13440 (word index)
#define SM_CG     (SM_PK + 2 * NNZP_)     // 15488
#define SM_FLOATS (SM_CG + NNZP_)         // 16512
#define SM_BYTES  (SM_FLOATS * 4)         // 66048

__global__ __launch_bounds__(THR, 2)
void wtp_kernel(const float* __restrict__ x1,
                const float* __restrict__ x2,
                const float* __restrict__ wgt,
                float* __restrict__ out)
{
    extern __shared__ float smem[];
    const int tid  = threadIdx.x;
    const int lane = tid & 31;
    const int wrp  = tid >> 5;

    // ---- stage: threads 0-255 -> batch0, 256-511 -> batch1 (coalesced float4) ----
    {
        const int half = tid >> 8;
        const int tl   = tid & 255;
        const int b    = blockIdx.x * BPB + half;
        float* sb = smem + half * SMB_;
        const float4* g1 = (const float4*)(x1 + (size_t)b * NM_ * C_);
        const float4* g2 = (const float4*)(x2 + (size_t)b * NM_ * C_);
        const float4* gw = (const float4*)(wgt + (size_t)b * NW_ * C_);
        float4* d1 = (float4*)sb;
        float4* d2 = (float4*)(sb + NM_ * C_);
        float4* dw = (float4*)(sb + 2 * NM_ * C_);
        #pragma unroll 2
        for (int i = tl; i < NM_*C_/4; i += 256) { d1[i] = g1[i]; d2[i] = g2[i]; }
        #pragma unroll 4
        for (int i = tl; i < NW_*C_/4; i += 256) { dw[i] = gw[i]; }
        // tables: 3072 words = 768 uint4, all 512 threads
        const uint4* gt = (const uint4*)g_tab;
        uint4* dt = (uint4*)(smem + SM_PK);
        #pragma unroll 2
        for (int i = tid; i < 3 * NNZP_ / 4; i += THR) dt[i] = gt[i];
    }
    __syncthreads();

    // ---- per-warp: 64-entry slice, applied to BOTH batches of this CTA ----
    const char* p1 = (const char*)smem + lane * 8;            // x1 batch0 (batch1 = +B1OFF)
    const char* p2 = (const char*)smem + X2OFF + lane * 8;    // x2 batch0
    const char* pw = (const char*)smem + WOFF  + lane * 8;    // w  batch0
    char* ob = (char*)(out + (size_t)(blockIdx.x * BPB) * NM_ * C_) + lane * 8;  // batch1 = +OB1

    const unsigned* s_pk = (const unsigned*)(smem + SM_PK);
    const float*    s_cg = smem + SM_CG;

    const int e0 = wrp * EPW_;
    const uint4*  tp = (const uint4*)(s_pk + 2 * e0);   // 2 entries per uint4 (LDS.128 broadcast)
    const float4* tc = (const float4*)(s_cg + e0);

    float ax0 = 0.f, ay0 = 0.f, ax1 = 0.f, ay1 = 0.f;
    float2 a0 = make_float2(0.f, 0.f);
    float2 a1 = make_float2(0.f, 0.f);                  // first entry of slice always flagged
    unsigned cur = s_pk[2 * e0 + 1] >> 16;              // mo*256 of first entry
    int first = 1;

    #define STEP(A, Bw, CGV) do {                                             \
        unsigned o1_ = (A) & 0xFFFFu;                                         \
        unsigned o2_ = (A) >> 16;                                             \
        unsigned ol_ = (Bw) & 0x3FFFu;                                        \
        unsigned om_ = (Bw) >> 16;                                            \
        if (om_ != cur) {  /* warp-uniform, rarely taken */                   \
            float* d0_ = (float*)(ob + cur);                                  \
            float* d1_ = (float*)(ob + cur + OB1);                            \
            if (first) {                                                      \
                atomicAdd(d0_, ax0); atomicAdd(d0_ + 1, ay0);                 \
                atomicAdd(d1_, ax1); atomicAdd(d1_ + 1, ay1);                 \
                first = 0;                                                    \
            } else {                                                          \
                *(float2*)d0_ = make_float2(ax0, ay0);                        \
                *(float2*)d1_ = make_float2(ax1, ay1);                        \
            }                                                                 \
            ax0 = 0.f; ay0 = 0.f; ax1 = 0.f; ay1 = 0.f; cur = om_;            \
        }                                                                     \
        if ((Bw) & 0x8000u) {                                                 \
            a0 = *(const float2*)(p1 + o1_);                                  \
            a1 = *(const float2*)(p1 + o1_ + B1OFF);                          \
        }                                                                     \
        float2 b0_ = *(const float2*)(p2 + o2_);                              \
        float2 b1_ = *(const float2*)(p2 + o2_ + B1OFF);                      \
        float2 w0_ = *(const float2*)(pw + ol_);                              \
        float2 w1_ = *(const float2*)(pw + ol_ + B1OFF);                      \
        ax0 = fmaf(a0.x * b0_.x, (CGV) * w0_.x, ax0);                         \
        ay0 = fmaf(a0.y * b0_.y, (CGV) * w0_.y, ay0);                         \
        ax1 = fmaf(a1.x * b1_.x, (CGV) * w1_.x, ax1);                         \
        ay1 = fmaf(a1.y * b1_.y, (CGV) * w1_.y, ay1);                         \
    } while (0)

    #pragma unroll 4
    for (int q = 0; q < EPW_ / 4; ++q) {
        uint4  u0 = tp[2*q];
        uint4  u1 = tp[2*q + 1];
        float4 c4 = tc[q];
        STEP(u0.x, u0.y, c4.x);
        STEP(u0.z, u0.w, c4.y);
        STEP(u1.x, u1.y, c4.z);
        STEP(u1.z, u1.w, c4.w);
    }
    // final segment may straddle next warp's slice -> atomic, both batches
    {
        float* d0 = (float*)(ob + cur);
        float* d1 = (float*)(ob + cur + OB1);
        atomicAdd(d0,     ax0);
        atomicAdd(d0 + 1, ay0);
        atomicAdd(d1,     ax1);
        atomicAdd(d1 + 1, ay1);
    }
}

extern "C" void kernel_launch(void* const* d_in, const int* in_sizes, int n_in,
                              void* d_out, int out_size)
{
    const float* x1  = (const float*)d_in[0];
    const float* x2  = (const float*)d_in[1];
    const float* wgt = (const float*)d_in[2];
    const float* cg  = (const float*)d_in[3];
    const int*   Mo  = (const int*)d_in[4];
    const int*   M1  = (const int*)d_in[5];
    const int*   M2  = (const int*)d_in[6];
    const int*   Li  = (const int*)d_in[7];
    float* out = (float*)d_out;

    cudaMemsetAsync(d_out, 0, (size_t)out_size * sizeof(float), 0);
    prep_kernel<<<1, 1024>>>(cg, Mo, M1, M2, Li);
    cudaFuncSetAttribute(wtp_kernel, cudaFuncAttributeMaxDynamicSharedMemorySize, SM_BYTES);
    wtp_kernel<<<GRID, THR, SM_BYTES>>>(x1, x2, wgt, out);
}

// round 9
// speedup vs baseline: 1.6293x; 1.2644x over previous
#include <cuda_runtime.h>
#include <cuda_fp16.h>
#include <cstdint>

// Problem constants
#define B_    4096
#define NM_   25
#define C_    64
#define NNZ_  1000
#define NW_   55
#define NNZP_ 1024          // padded (16 warps x 64 entries)
#define EPW_  64            // entries per warp slice
#define NBINP 640

#define THR   512           // 16 warps; each warp: 64-entry slice x BOTH batches
#define BPB   2
#define GRID  (B_ / BPB)    // 2048

// Reordered tables (batch-independent), rebuilt by prep every launch.
// layout (words): [0 .. 2*NNZP_): per entry {A = o1|o2h<<16, B = olh|flag<<15|om<<16}
//   o1 = m1*256 (fp32 row byte off), o2h = m2*128 (half row), olh = li*128, om = mo*256
//                 [2*NNZP_ .. 3*NNZP_): cg bits
__device__ unsigned g_tab[3 * NNZP_];

// ---------------- prep: counting-sort by (mo,m1), pre-shift byte offsets, set load-a flags ----------------
__global__ __launch_bounds__(1024, 1)
void prep_kernel(const float* __restrict__ cg,
                 const int* __restrict__ Mo,  const int* __restrict__ M1,
                 const int* __restrict__ M2,  const int* __restrict__ Li)
{
    __shared__ int      hist[NBINP];
    __shared__ unsigned sA[NNZP_], sB[NNZP_];
    __shared__ float    sC[NNZP_];
    __shared__ short    skey[NNZP_];
    __shared__ int      wsum[32];

    const int tid  = threadIdx.x;
    const int lane = tid & 31;
    const int wrp  = tid >> 5;

    if (tid < NBINP) hist[tid] = 0;
    __syncthreads();

    int key = 0;
    if (tid < NNZ_) {
        key = Mo[tid] * 25 + M1[tid];
        atomicAdd(&hist[key], 1);
    }
    __syncthreads();

    // exclusive scan over 640 bins
    if (wrp < 20) {
        int bin = wrp * 32 + lane;
        int v = hist[bin];
        int inc = v;
        #pragma unroll
        for (int d = 1; d < 32; d <<= 1) {
            int t = __shfl_up_sync(0xFFFFFFFFu, inc, d);
            if (lane >= d) inc += t;
        }
        if (lane == 31) wsum[wrp] = inc;
        hist[bin] = inc - v;
    }
    __syncthreads();
    if (wrp == 0) {
        int v = (lane < 20) ? wsum[lane] : 0;
        int inc = v;
        #pragma unroll
        for (int d = 1; d < 32; d <<= 1) {
            int t = __shfl_up_sync(0xFFFFFFFFu, inc, d);
            if (lane >= d) inc += t;
        }
        if (lane < 20) wsum[lane] = inc - v;
    }
    __syncthreads();
    if (wrp < 20) hist[wrp * 32 + lane] += wsum[wrp];
    __syncthreads();

    // scatter (order within a (mo,m1) bin arbitrary: sum reassociation only)
    if (tid < NNZ_) {
        int idx = atomicAdd(&hist[key], 1);
        sA[idx] = ((unsigned)M1[tid] << 8) | ((unsigned)M2[tid] << (7 + 16));
        sB[idx] = ((unsigned)Li[tid] << 7) | ((unsigned)Mo[tid] << (8 + 16));
        sC[idx] = cg[tid];
        skey[idx] = (short)key;
    }
    __syncthreads();

    // pads + load-a flags (slice boundary every EPW_=64 entries) + writeout
    if (tid < NNZP_) {
        unsigned A, Bw; float Cv;
        if (tid < NNZ_) {
            A = sA[tid]; Bw = sB[tid]; Cv = sC[tid];
            int f = (tid == 0) || ((tid & (EPW_ - 1)) == 0) || (skey[tid] != skey[tid - 1]);
            if (f) Bw |= 0x8000u;
        } else {
            A = 0; Bw = sB[NNZ_ - 1] & 0xFFFF0000u; Cv = 0.f;  // cg=0 dummy, same mo as last
        }
        g_tab[2 * tid]         = A;
        g_tab[2 * tid + 1]     = Bw;
        g_tab[2 * NNZP_ + tid] = __float_as_uint(Cv);
    }
}

// ---------------- main kernel ----------------
// SMEM byte layout:
//  [0,6400)       x1 b0 (fp32)        [6400,12800)   x1 b1
//  [12800,16000)  x2 b0 (half)        [16000,19200)  x2 b1
//  [19200,26240)  w  b0 (half)        [26240,33280)  w  b1
//  [33280,41472)  pk (8192 B)         [41472,45568)  cg (4096 B)
#define X1OFF   0
#define X1B1    6400
#define X2OFF   12800
#define X2B1    3200
#define WOFF    19200
#define WB1     7040
#define PKOFF   33280
#define CGOFF   41472
#define SM_BYTES 45568
#define OB1     (NM_*C_*4)   // 6400 B: batch1 offset in out

__global__ __launch_bounds__(THR, 2)
void wtp_kernel(const float* __restrict__ x1,
                const float* __restrict__ x2,
                const float* __restrict__ wgt,
                float* __restrict__ out)
{
    extern __shared__ char smem[];
    const int tid  = threadIdx.x;
    const int lane = tid & 31;
    const int wrp  = tid >> 5;

    // ---- stage: threads 0-255 -> batch0, 256-511 -> batch1 ----
    {
        const int half = tid >> 8;
        const int tl   = tid & 255;
        const int b    = blockIdx.x * BPB + half;
        // x1: fp32 copy (400 float4)
        const float4* g1 = (const float4*)(x1 + (size_t)b * NM_ * C_);
        float4* d1 = (float4*)(smem + X1OFF + half * X1B1);
        #pragma unroll 2
        for (int i = tl; i < NM_*C_/4; i += 256) d1[i] = g1[i];
        // x2: fp32 -> half2 (400 float4 -> uint2)
        const float4* g2 = (const float4*)(x2 + (size_t)b * NM_ * C_);
        uint2* d2 = (uint2*)(smem + X2OFF + half * X2B1);
        #pragma unroll 2
        for (int i = tl; i < NM_*C_/4; i += 256) {
            float4 v = g2[i];
            __half2 h0 = __floats2half2_rn(v.x, v.y);
            __half2 h1 = __floats2half2_rn(v.z, v.w);
            d2[i] = make_uint2(*(unsigned*)&h0, *(unsigned*)&h1);
        }
        // w: fp32 -> half2 (880 float4)
        const float4* gw = (const float4*)(wgt + (size_t)b * NW_ * C_);
        uint2* dw = (uint2*)(smem + WOFF + half * WB1);
        #pragma unroll 4
        for (int i = tl; i < NW_*C_/4; i += 256) {
            float4 v = gw[i];
            __half2 h0 = __floats2half2_rn(v.x, v.y);
            __half2 h1 = __floats2half2_rn(v.z, v.w);
            dw[i] = make_uint2(*(unsigned*)&h0, *(unsigned*)&h1);
        }
        // tables: 3072 words = 768 uint4, all 512 threads
        const uint4* gt = (const uint4*)g_tab;
        uint4* dt = (uint4*)(smem + PKOFF);
        #pragma unroll 2
        for (int i = tid; i < 3 * NNZP_ / 4; i += THR) dt[i] = gt[i];
    }
    __syncthreads();

    // ---- per-warp: 64-entry slice, both batches; lanes = channel pairs ----
    const char* p1 = smem + X1OFF + lane * 8;   // fp32 float2; batch1 = +X1B1
    const char* p2 = smem + X2OFF + lane * 4;   // half2;      batch1 = +X2B1
    const char* pw = smem + WOFF  + lane * 4;   // half2;      batch1 = +WB1
    char* ob = (char*)(out + (size_t)(blockIdx.x * BPB) * NM_ * C_) + lane * 8;

    const unsigned* s_pk = (const unsigned*)(smem + PKOFF);
    const float*    s_cg = (const float*)(smem + CGOFF);

    const int e0 = wrp * EPW_;
    const uint4*  tp = (const uint4*)(s_pk + 2 * e0);
    const float4* tc = (const float4*)(s_cg + e0);

    float ax0 = 0.f, ay0 = 0.f, ax1 = 0.f, ay1 = 0.f;
    float2 a0 = make_float2(0.f, 0.f);
    float2 a1 = make_float2(0.f, 0.f);              // first entry of slice always flagged
    unsigned cur = s_pk[2 * e0 + 1] >> 16;          // mo*256 of first entry
    int first = 1;

    #define STEP(A, Bw, CGV) do {                                             \
        unsigned o1_ = (A) & 0xFFFFu;                                         \
        unsigned o2_ = (A) >> 16;                                             \
        unsigned ol_ = (Bw) & 0x3FFFu;                                        \
        unsigned om_ = (Bw) >> 16;                                            \
        if (om_ != cur) {  /* warp-uniform, rarely taken */                   \
            float* d0_ = (float*)(ob + cur);                                  \
            float* d1_ = (float*)(ob + cur + OB1);                            \
            if (first) {                                                      \
                atomicAdd(d0_, ax0); atomicAdd(d0_ + 1, ay0);                 \
                atomicAdd(d1_, ax1); atomicAdd(d1_ + 1, ay1);                 \
                first = 0;                                                    \
            } else {                                                          \
                *(float2*)d0_ = make_float2(ax0, ay0);                        \
                *(float2*)d1_ = make_float2(ax1, ay1);                        \
            }                                                                 \
            ax0 = 0.f; ay0 = 0.f; ax1 = 0.f; ay1 = 0.f; cur = om_;            \
        }                                                                     \
        if ((Bw) & 0x8000u) {                                                 \
            a0 = *(const float2*)(p1 + o1_);                                  \
            a1 = *(const float2*)(p1 + o1_ + X1B1);                           \
        }                                                                     \
        __half2 b0h = *(const __half2*)(p2 + o2_);                            \
        __half2 b1h = *(const __half2*)(p2 + o2_ + X2B1);                     \
        __half2 w0h = *(const __half2*)(pw + ol_);                            \
        __half2 w1h = *(const __half2*)(pw + ol_ + WB1);                      \
        float2 s0 = __half22float2(__hmul2(b0h, w0h));                        \
        float2 s1 = __half22float2(__hmul2(b1h, w1h));                        \
        ax0 = fmaf(a0.x * s0.x, (CGV), ax0);                                  \
        ay0 = fmaf(a0.y * s0.y, (CGV), ay0);                                  \
        ax1 = fmaf(a1.x * s1.x, (CGV), ax1);                                  \
        ay1 = fmaf(a1.y * s1.y, (CGV), ay1);                                  \
    } while (0)

    #pragma unroll 4
    for (int q = 0; q < EPW_ / 4; ++q) {
        uint4  u0 = tp[2*q];
        uint4  u1 = tp[2*q + 1];
        float4 c4 = tc[q];
        STEP(u0.x, u0.y, c4.x);
        STEP(u0.z, u0.w, c4.y);
        STEP(u1.x, u1.y, c4.z);
        STEP(u1.z, u1.w, c4.w);
    }
    // final segment may straddle next warp's slice -> atomic, both batches
    {
        float* d0 = (float*)(ob + cur);
        float* d1 = (float*)(ob + cur + OB1);
        atomicAdd(d0,     ax0);
        atomicAdd(d0 + 1, ay0);
        atomicAdd(d1,     ax1);
        atomicAdd(d1 + 1, ay1);
    }
}

extern "C" void kernel_launch(void* const* d_in, const int* in_sizes, int n_in,
                              void* d_out, int out_size)
{
    const float* x1  = (const float*)d_in[0];
    const float* x2  = (const float*)d_in[1];
    const float* wgt = (const float*)d_in[2];
    const float* cg  = (const float*)d_in[3];
    const int*   Mo  = (const int*)d_in[4];
    const int*   M1  = (const int*)d_in[5];
    const int*   M2  = (const int*)d_in[6];
    const int*   Li  = (const int*)d_in[7];
    float* out = (float*)d_out;

    cudaMemsetAsync(d_out, 0, (size_t)out_size * sizeof(float), 0);
    prep_kernel<<<1, 1024>>>(cg, Mo, M1, M2, Li);
    cudaFuncSetAttribute(wtp_kernel, cudaFuncAttributeMaxDynamicSharedMemorySize, SM_BYTES);
    wtp_kernel<<<GRID, THR, SM_BYTES>>>(x1, x2, wgt, out);
}

// round 10
// speedup vs baseline: 1.9246x; 1.1812x over previous
#include <cuda_runtime.h>
#include <cuda_fp16.h>
#include <cstdint>

// Problem constants
#define B_    4096
#define NM_   25
#define C_    64
#define NNZ_  1000
#define NW_   55
#define NNZP_ 1024          // padded (16 warps x 64 entries)
#define EPW_  64            // entries per warp slice
#define NBINP 640

#define THR   512           // 16 warps; each warp: 64-entry slice x FOUR batches
#define BPB   4
#define GRID  (B_ / BPB)    // 1024

// Reordered tables (batch-independent), rebuilt by prep every launch.
// layout (words): [0 .. 2*NNZP_): per entry {A = o1|o2<<16, B = ol|flag<<15|om<<16}
//   o1 = m1*128, o2 = m2*128, ol = li*128 (half rows), om = mo*256 (fp32 out row)
//                 [2*NNZP_ .. 3*NNZP_): cg bits
__device__ unsigned g_tab[3 * NNZP_];

// ---------------- prep: counting-sort by (mo,m1), pre-shift byte offsets, set load-a flags ----------------
__global__ __launch_bounds__(1024, 1)
void prep_kernel(const float* __restrict__ cg,
                 const int* __restrict__ Mo,  const int* __restrict__ M1,
                 const int* __restrict__ M2,  const int* __restrict__ Li)
{
    __shared__ int      hist[NBINP];
    __shared__ unsigned sA[NNZP_], sB[NNZP_];
    __shared__ float    sC[NNZP_];
    __shared__ short    skey[NNZP_];
    __shared__ int      wsum[32];

    const int tid  = threadIdx.x;
    const int lane = tid & 31;
    const int wrp  = tid >> 5;

    if (tid < NBINP) hist[tid] = 0;
    __syncthreads();

    int key = 0;
    if (tid < NNZ_) {
        key = Mo[tid] * 25 + M1[tid];
        atomicAdd(&hist[key], 1);
    }
    __syncthreads();

    // exclusive scan over 640 bins
    if (wrp < 20) {
        int bin = wrp * 32 + lane;
        int v = hist[bin];
        int inc = v;
        #pragma unroll
        for (int d = 1; d < 32; d <<= 1) {
            int t = __shfl_up_sync(0xFFFFFFFFu, inc, d);
            if (lane >= d) inc += t;
        }
        if (lane == 31) wsum[wrp] = inc;
        hist[bin] = inc - v;
    }
    __syncthreads();
    if (wrp == 0) {
        int v = (lane < 20) ? wsum[lane] : 0;
        int inc = v;
        #pragma unroll
        for (int d = 1; d < 32; d <<= 1) {
            int t = __shfl_up_sync(0xFFFFFFFFu, inc, d);
            if (lane >= d) inc += t;
        }
        if (lane < 20) wsum[lane] = inc - v;
    }
    __syncthreads();
    if (wrp < 20) hist[wrp * 32 + lane] += wsum[wrp];
    __syncthreads();

    // scatter (order within a (mo,m1) bin arbitrary: sum reassociation only)
    if (tid < NNZ_) {
        int idx = atomicAdd(&hist[key], 1);
        sA[idx] = ((unsigned)M1[tid] << 7) | ((unsigned)M2[tid] << (7 + 16));
        sB[idx] = ((unsigned)Li[tid] << 7) | ((unsigned)Mo[tid] << (8 + 16));
        sC[idx] = cg[tid];
        skey[idx] = (short)key;
    }
    __syncthreads();

    // pads + load-a flags (slice boundary every EPW_=64 entries) + writeout
    if (tid < NNZP_) {
        unsigned A, Bw; float Cv;
        if (tid < NNZ_) {
            A = sA[tid]; Bw = sB[tid]; Cv = sC[tid];
            int f = (tid == 0) || ((tid & (EPW_ - 1)) == 0) || (skey[tid] != skey[tid - 1]);
            if (f) Bw |= 0x8000u;
        } else {
            A = 0; Bw = sB[NNZ_ - 1] & 0xFFFF0000u; Cv = 0.f;  // cg=0 dummy, same mo as last
        }
        g_tab[2 * tid]         = A;
        g_tab[2 * tid + 1]     = Bw;
        g_tab[2 * NNZP_ + tid] = __float_as_uint(Cv);
    }
}

// ---------------- main kernel ----------------
// SMEM byte layout (all operands half2):
//  [0,12800)       x1: 4 batches x 3200 B
//  [12800,25600)   x2: 4 batches x 3200 B
//  [25600,53760)   w : 4 batches x 7040 B
//  [53760,61952)   pk (8192 B)
//  [61952,66048)   cg (4096 B)
#define X1OFF   0
#define X1SZ    3200
#define X2OFF   12800
#define X2SZ    3200
#define WOFF    25600
#define WSZ     7040
#define PKOFF   53760
#define CGOFF   61952
#define SM_BYTES 66048
#define OBSZ    (NM_*C_*4)   // 6400 B: per-batch stride in out

__global__ __launch_bounds__(THR, 2)
void wtp_kernel(const float* __restrict__ x1,
                const float* __restrict__ x2,
                const float* __restrict__ wgt,
                float* __restrict__ out)
{
    extern __shared__ char smem[];
    const int tid  = threadIdx.x;
    const int lane = tid & 31;
    const int wrp  = tid >> 5;

    // ---- stage: 128 threads per batch (4 batches), fp32 -> half2 ----
    {
        const int sub = tid >> 7;        // 0..3
        const int tl  = tid & 127;
        const int b   = blockIdx.x * BPB + sub;
        const float4* g1 = (const float4*)(x1 + (size_t)b * NM_ * C_);
        const float4* g2 = (const float4*)(x2 + (size_t)b * NM_ * C_);
        const float4* gw = (const float4*)(wgt + (size_t)b * NW_ * C_);
        uint2* d1 = (uint2*)(smem + X1OFF + sub * X1SZ);
        uint2* d2 = (uint2*)(smem + X2OFF + sub * X2SZ);
        uint2* dw = (uint2*)(smem + WOFF  + sub * WSZ);
        #pragma unroll 2
        for (int i = tl; i < NM_*C_/4; i += 128) {
            float4 v1 = g1[i];
            float4 v2 = g2[i];
            __half2 a0 = __floats2half2_rn(v1.x, v1.y);
            __half2 a1 = __floats2half2_rn(v1.z, v1.w);
            __half2 b0 = __floats2half2_rn(v2.x, v2.y);
            __half2 b1 = __floats2half2_rn(v2.z, v2.w);
            d1[i] = make_uint2(*(unsigned*)&a0, *(unsigned*)&a1);
            d2[i] = make_uint2(*(unsigned*)&b0, *(unsigned*)&b1);
        }
        #pragma unroll 2
        for (int i = tl; i < NW_*C_/4; i += 128) {
            float4 v = gw[i];
            __half2 h0 = __floats2half2_rn(v.x, v.y);
            __half2 h1 = __floats2half2_rn(v.z, v.w);
            dw[i] = make_uint2(*(unsigned*)&h0, *(unsigned*)&h1);
        }
        // tables: 3072 words = 768 uint4, all 512 threads
        const uint4* gt = (const uint4*)g_tab;
        uint4* dt = (uint4*)(smem + PKOFF);
        #pragma unroll 2
        for (int i = tid; i < 3 * NNZP_ / 4; i += THR) dt[i] = gt[i];
    }
    __syncthreads();

    // ---- per-warp: 64-entry slice, 4 batches; lanes = half2 channel pairs ----
    const char* p1 = smem + X1OFF + lane * 4;   // batch k at +k*X1SZ (immediate)
    const char* p2 = smem + X2OFF + lane * 4;
    const char* pw = smem + WOFF  + lane * 4;
    char* ob = (char*)(out + (size_t)(blockIdx.x * BPB) * NM_ * C_) + lane * 8;

    const unsigned* s_pk = (const unsigned*)(smem + PKOFF);
    const float*    s_cg = (const float*)(smem + CGOFF);

    const int e0 = wrp * EPW_;
    const uint4*  tp = (const uint4*)(s_pk + 2 * e0);
    const float4* tc = (const float4*)(s_cg + e0);

    float ax0=0.f, ay0=0.f, ax1=0.f, ay1=0.f, ax2=0.f, ay2=0.f, ax3=0.f, ay3=0.f;
    __half2 a0 = __float2half2_rn(0.f), a1 = a0, a2 = a0, a3 = a0;  // first entry always flagged
    unsigned cur = s_pk[2 * e0 + 1] >> 16;          // mo*256 of first entry
    int first = 1;

    #define STEP(A, Bw, CGV) do {                                             \
        unsigned o1_ = (A) & 0xFFFFu;                                         \
        unsigned o2_ = (A) >> 16;                                             \
        unsigned ol_ = (Bw) & 0x3FFFu;                                        \
        unsigned om_ = (Bw) >> 16;                                            \
        if (om_ != cur) {  /* warp-uniform, rarely taken */                   \
            float* d0_ = (float*)(ob + cur);                                  \
            float* d1_ = (float*)(ob + cur + OBSZ);                           \
            float* d2_ = (float*)(ob + cur + 2*OBSZ);                         \
            float* d3_ = (float*)(ob + cur + 3*OBSZ);                         \
            if (first) {                                                      \
                atomicAdd(d0_, ax0); atomicAdd(d0_ + 1, ay0);                 \
                atomicAdd(d1_, ax1); atomicAdd(d1_ + 1, ay1);                 \
                atomicAdd(d2_, ax2); atomicAdd(d2_ + 1, ay2);                 \
                atomicAdd(d3_, ax3); atomicAdd(d3_ + 1, ay3);                 \
                first = 0;                                                    \
            } else {                                                          \
                *(float2*)d0_ = make_float2(ax0, ay0);                        \
                *(float2*)d1_ = make_float2(ax1, ay1);                        \
                *(float2*)d2_ = make_float2(ax2, ay2);                        \
                *(float2*)d3_ = make_float2(ax3, ay3);                        \
            }                                                                 \
            ax0=0.f; ay0=0.f; ax1=0.f; ay1=0.f;                               \
            ax2=0.f; ay2=0.f; ax3=0.f; ay3=0.f; cur = om_;                    \
        }                                                                     \
        if ((Bw) & 0x8000u) {                                                 \
            a0 = *(const __half2*)(p1 + o1_);                                 \
            a1 = *(const __half2*)(p1 + o1_ + X1SZ);                          \
            a2 = *(const __half2*)(p1 + o1_ + 2*X1SZ);                        \
            a3 = *(const __half2*)(p1 + o1_ + 3*X1SZ);                        \
        }                                                                     \
        __half2 b0h = *(const __half2*)(p2 + o2_);                            \
        __half2 b1h = *(const __half2*)(p2 + o2_ + X2SZ);                     \
        __half2 b2h = *(const __half2*)(p2 + o2_ + 2*X2SZ);                   \
        __half2 b3h = *(const __half2*)(p2 + o2_ + 3*X2SZ);                   \
        __half2 w0h = *(const __half2*)(pw + ol_);                            \
        __half2 w1h = *(const __half2*)(pw + ol_ + WSZ);                      \
        __half2 w2h = *(const __half2*)(pw + ol_ + 2*WSZ);                    \
        __half2 w3h = *(const __half2*)(pw + ol_ + 3*WSZ);                    \
        float2 s0 = __half22float2(__hmul2(__hmul2(b0h, w0h), a0));           \
        float2 s1 = __half22float2(__hmul2(__hmul2(b1h, w1h), a1));           \
        float2 s2 = __half22float2(__hmul2(__hmul2(b2h, w2h), a2));           \
        float2 s3 = __half22float2(__hmul2(__hmul2(b3h, w3h), a3));           \
        ax0 = fmaf(s0.x, (CGV), ax0);  ay0 = fmaf(s0.y, (CGV), ay0);          \
        ax1 = fmaf(s1.x, (CGV), ax1);  ay1 = fmaf(s1.y, (CGV), ay1);          \
        ax2 = fmaf(s2.x, (CGV), ax2);  ay2 = fmaf(s2.y, (CGV), ay2);          \
        ax3 = fmaf(s3.x, (CGV), ax3);  ay3 = fmaf(s3.y, (CGV), ay3);          \
    } while (0)

    #pragma unroll 2
    for (int q = 0; q < EPW_ / 4; ++q) {
        uint4  u0 = tp[2*q];
        uint4  u1 = tp[2*q + 1];
        float4 c4 = tc[q];
        STEP(u0.x, u0.y, c4.x);
        STEP(u0.z, u0.w, c4.y);
        STEP(u1.x, u1.y, c4.z);
        STEP(u1.z, u1.w, c4.w);
    }
    // final segment may straddle next warp's slice -> atomic, all batches
    {
        float* d0 = (float*)(ob + cur);
        float* d1 = (float*)(ob + cur + OBSZ);
        float* d2 = (float*)(ob + cur + 2*OBSZ);
        float* d3 = (float*)(ob + cur + 3*OBSZ);
        atomicAdd(d0, ax0); atomicAdd(d0 + 1, ay0);
        atomicAdd(d1, ax1); atomicAdd(d1 + 1, ay1);
        atomicAdd(d2, ax2); atomicAdd(d2 + 1, ay2);
        atomicAdd(d3, ax3); atomicAdd(d3 + 1, ay3);
    }
}

extern "C" void kernel_launch(void* const* d_in, const int* in_sizes, int n_in,
                              void* d_out, int out_size)
{
    const float* x1  = (const float*)d_in[0];
    const float* x2  = (const float*)d_in[1];
    const float* wgt = (const float*)d_in[2];
    const float* cg  = (const float*)d_in[3];
    const int*   Mo  = (const int*)d_in[4];
    const int*   M1  = (const int*)d_in[5];
    const int*   M2  = (const int*)d_in[6];
    const int*   Li  = (const int*)d_in[7];
    float* out = (float*)d_out;

    cudaMemsetAsync(d_out, 0, (size_t)out_size * sizeof(float), 0);
    prep_kernel<<<1, 1024>>>(cg, Mo, M1, M2, Li);
    cudaFuncSetAttribute(wtp_kernel, cudaFuncAttributeMaxDynamicSharedMemorySize, SM_BYTES);
    wtp_kernel<<<GRID, THR, SM_BYTES>>>(x1, x2, wgt, out);
}

// round 11
// speedup vs baseline: 2.0270x; 1.0532x over previous
#include <cuda_runtime.h>
#include <cuda_fp16.h>
#include <cstdint>

// Problem constants
#define B_    4096
#define NM_   25
#define C_    64
#define NNZ_  1000
#define NW_   55
#define NNZP_ 1024          // padded (16 warps x 64 entries)
#define EPW_  64            // entries per warp slice
#define NBINP 640

#define THR   512           // 16 warps; each warp: 64-entry slice x FOUR batches
#define BPB   4
#define GRID  (B_ / BPB)    // 1024

// Reordered tables (batch-independent), rebuilt by prep every launch.
// layout (words): [0 .. 2*NNZP_): per entry {A = o1 | flag<<15 | o2<<16, B = ol | om<<16}
//   o1 = m1*512, o2 = m2*512, ol = li*512 (interleaved half rows), om = mo*256 (fp32 out row)
//                 [2*NNZP_ .. 3*NNZP_): cg bits
__device__ unsigned g_tab[3 * NNZP_];

// ---------------- prep: counting-sort by (mo,m1), pre-shift byte offsets, set load-a flags ----------------
__global__ __launch_bounds__(1024, 1)
void prep_kernel(const float* __restrict__ cg,
                 const int* __restrict__ Mo,  const int* __restrict__ M1,
                 const int* __restrict__ M2,  const int* __restrict__ Li)
{
    __shared__ int      hist[NBINP];
    __shared__ unsigned sA[NNZP_], sB[NNZP_];
    __shared__ float    sC[NNZP_];
    __shared__ short    skey[NNZP_];
    __shared__ int      wsum[32];

    const int tid  = threadIdx.x;
    const int lane = tid & 31;
    const int wrp  = tid >> 5;

    if (tid < NBINP) hist[tid] = 0;
    __syncthreads();

    int key = 0;
    if (tid < NNZ_) {
        key = Mo[tid] * 25 + M1[tid];
        atomicAdd(&hist[key], 1);
    }
    __syncthreads();

    // exclusive scan over 640 bins
    if (wrp < 20) {
        int bin = wrp * 32 + lane;
        int v = hist[bin];
        int inc = v;
        #pragma unroll
        for (int d = 1; d < 32; d <<= 1) {
            int t = __shfl_up_sync(0xFFFFFFFFu, inc, d);
            if (lane >= d) inc += t;
        }
        if (lane == 31) wsum[wrp] = inc;
        hist[bin] = inc - v;
    }
    __syncthreads();
    if (wrp == 0) {
        int v = (lane < 20) ? wsum[lane] : 0;
        int inc = v;
        #pragma unroll
        for (int d = 1; d < 32; d <<= 1) {
            int t = __shfl_up_sync(0xFFFFFFFFu, inc, d);
            if (lane >= d) inc += t;
        }
        if (lane < 20) wsum[lane] = inc - v;
    }
    __syncthreads();
    if (wrp < 20) hist[wrp * 32 + lane] += wsum[wrp];
    __syncthreads();

    // scatter (order within a (mo,m1) bin arbitrary: sum reassociation only)
    if (tid < NNZ_) {
        int idx = atomicAdd(&hist[key], 1);
        sA[idx] = ((unsigned)M1[tid] << 9) | ((unsigned)M2[tid] << (9 + 16));
        sB[idx] = ((unsigned)Li[tid] << 9) | ((unsigned)Mo[tid] << (8 + 16));
        sC[idx] = cg[tid];
        skey[idx] = (short)key;
    }
    __syncthreads();

    // pads + load-a flags (slice boundary every EPW_=64 entries) + writeout
    if (tid < NNZP_) {
        unsigned A, Bw; float Cv;
        if (tid < NNZ_) {
            A = sA[tid]; Bw = sB[tid]; Cv = sC[tid];
            int f = (tid == 0) || ((tid & (EPW_ - 1)) == 0) || (skey[tid] != skey[tid - 1]);
            if (f) A |= 0x8000u;                      // flag now in A bit 15
        } else {
            A = 0; Bw = sB[NNZ_ - 1] & 0xFFFF0000u; Cv = 0.f;  // cg=0 dummy, same mo as last
        }
        g_tab[2 * tid]         = A;
        g_tab[2 * tid + 1]     = Bw;
        g_tab[2 * NNZP_ + tid] = __float_as_uint(Cv);
    }
}

// ---------------- main kernel ----------------
// SMEM byte layout (operands half2, 4 batches interleaved per row: row*512 + pair*16 + batch*4):
//  [0,12800)       x1 (25 rows x 512 B)
//  [12800,25600)   x2
//  [25600,53760)   w  (55 rows x 512 B)
//  [53760,61952)   pk (8192 B)
//  [61952,66048)   cg (4096 B)
#define X1OFF   0
#define X2OFF   12800
#define WOFF    25600
#define PKOFF   53760
#define CGOFF   61952
#define SM_BYTES 66048
#define OBSZ    (NM_*C_*4)   // 6400 B: per-batch stride in out

__global__ __launch_bounds__(THR, 2)
void wtp_kernel(const float* __restrict__ x1,
                const float* __restrict__ x2,
                const float* __restrict__ wgt,
                float* __restrict__ out)
{
    extern __shared__ char smem[];
    const int tid  = threadIdx.x;
    const int lane = tid & 31;
    const int wrp  = tid >> 5;
    const int bbase = blockIdx.x * BPB;

    float* outbase = out + (size_t)bbase * NM_ * C_;

    // ---- stage: gather 4 batches per pair-index, interleave, STS.128 ----
    {
        // x1 & x2: 800 channel-pairs each
        const float2* g10 = (const float2*)(x1 + (size_t)bbase * NM_ * C_);
        const float2* g20 = (const float2*)(x2 + (size_t)bbase * NM_ * C_);
        uint4* d1 = (uint4*)(smem + X1OFF);
        uint4* d2 = (uint4*)(smem + X2OFF);
        for (int i = tid; i < NM_ * C_ / 2; i += THR) {
            float2 a0 = g10[i];
            float2 a1 = g10[i + 1 * NM_ * C_ / 2];
            float2 a2 = g10[i + 2 * NM_ * C_ / 2];
            float2 a3 = g10[i + 3 * NM_ * C_ / 2];
            __half2 h0 = __floats2half2_rn(a0.x, a0.y);
            __half2 h1 = __floats2half2_rn(a1.x, a1.y);
            __half2 h2 = __floats2half2_rn(a2.x, a2.y);
            __half2 h3 = __floats2half2_rn(a3.x, a3.y);
            d1[i] = make_uint4(*(unsigned*)&h0, *(unsigned*)&h1,
                               *(unsigned*)&h2, *(unsigned*)&h3);
            float2 b0 = g20[i];
            float2 b1 = g20[i + 1 * NM_ * C_ / 2];
            float2 b2 = g20[i + 2 * NM_ * C_ / 2];
            float2 b3 = g20[i + 3 * NM_ * C_ / 2];
            h0 = __floats2half2_rn(b0.x, b0.y);
            h1 = __floats2half2_rn(b1.x, b1.y);
            h2 = __floats2half2_rn(b2.x, b2.y);
            h3 = __floats2half2_rn(b3.x, b3.y);
            d2[i] = make_uint4(*(unsigned*)&h0, *(unsigned*)&h1,
                               *(unsigned*)&h2, *(unsigned*)&h3);
        }
        // w: 1760 channel-pairs
        const float2* gw0 = (const float2*)(wgt + (size_t)bbase * NW_ * C_);
        uint4* dw = (uint4*)(smem + WOFF);
        for (int i = tid; i < NW_ * C_ / 2; i += THR) {
            float2 w0 = gw0[i];
            float2 w1 = gw0[i + 1 * NW_ * C_ / 2];
            float2 w2 = gw0[i + 2 * NW_ * C_ / 2];
            float2 w3 = gw0[i + 3 * NW_ * C_ / 2];
            __half2 h0 = __floats2half2_rn(w0.x, w0.y);
            __half2 h1 = __floats2half2_rn(w1.x, w1.y);
            __half2 h2 = __floats2half2_rn(w2.x, w2.y);
            __half2 h3 = __floats2half2_rn(w3.x, w3.y);
            dw[i] = make_uint4(*(unsigned*)&h0, *(unsigned*)&h1,
                               *(unsigned*)&h2, *(unsigned*)&h3);
        }
        // tables: 3072 words = 768 uint4
        const uint4* gt = (const uint4*)g_tab;
        uint4* dt = (uint4*)(smem + PKOFF);
        #pragma unroll 2
        for (int i = tid; i < 3 * NNZP_ / 4; i += THR) dt[i] = gt[i];
        // zero this CTA's output slab (replaces global memset; atomics need zeros)
        float4 z = make_float4(0.f, 0.f, 0.f, 0.f);
        float4* oz = (float4*)outbase;
        for (int i = tid; i < BPB * NM_ * C_ / 4; i += THR) oz[i] = z;
    }
    __syncthreads();

    // ---- per-warp: 64-entry slice, 4 batches; lanes = channel pairs, LDS.128 per operand ----
    const char* p1 = smem + X1OFF + lane * 16;
    const char* p2 = smem + X2OFF + lane * 16;
    const char* pw = smem + WOFF  + lane * 16;
    char* ob = (char*)outbase + lane * 8;

    const unsigned* s_pk = (const unsigned*)(smem + PKOFF);
    const float*    s_cg = (const float*)(smem + CGOFF);

    const int e0 = wrp * EPW_;
    const uint4*  tp = (const uint4*)(s_pk + 2 * e0);
    const float4* tc = (const float4*)(s_cg + e0);

    float ax0=0.f, ay0=0.f, ax1=0.f, ay1=0.f, ax2=0.f, ay2=0.f, ax3=0.f, ay3=0.f;
    uint4 A4 = make_uint4(0u, 0u, 0u, 0u);          // x1 cache (first entry always flagged)
    unsigned cur = s_pk[2 * e0 + 1] >> 16;          // mo*256 of first entry
    int first = 1;

    #define STEP(Aw, Bw, CGV) do {                                            \
        unsigned o1_ = (Aw) & 0x3FFFu;                                        \
        unsigned o2_ = (Aw) >> 16;                                            \
        unsigned ol_ = (Bw) & 0xFFFFu;                                        \
        unsigned om_ = (Bw) >> 16;                                            \
        if (om_ != cur) {  /* warp-uniform, rarely taken */                   \
            float* d0_ = (float*)(ob + cur);                                  \
            float* d1_ = (float*)(ob + cur + OBSZ);                           \
            float* d2_ = (float*)(ob + cur + 2*OBSZ);                         \
            float* d3_ = (float*)(ob + cur + 3*OBSZ);                         \
            if (first) {                                                      \
                atomicAdd(d0_, ax0); atomicAdd(d0_ + 1, ay0);                 \
                atomicAdd(d1_, ax1); atomicAdd(d1_ + 1, ay1);                 \
                atomicAdd(d2_, ax2); atomicAdd(d2_ + 1, ay2);                 \
                atomicAdd(d3_, ax3); atomicAdd(d3_ + 1, ay3);                 \
                first = 0;                                                    \
            } else {                                                          \
                *(float2*)d0_ = make_float2(ax0, ay0);                        \
                *(float2*)d1_ = make_float2(ax1, ay1);                        \
                *(float2*)d2_ = make_float2(ax2, ay2);                        \
                *(float2*)d3_ = make_float2(ax3, ay3);                        \
            }                                                                 \
            ax0=0.f; ay0=0.f; ax1=0.f; ay1=0.f;                               \
            ax2=0.f; ay2=0.f; ax3=0.f; ay3=0.f; cur = om_;                    \
        }                                                                     \
        if ((Aw) & 0x8000u) A4 = *(const uint4*)(p1 + o1_);                   \
        uint4 B4 = *(const uint4*)(p2 + o2_);                                 \
        uint4 W4 = *(const uint4*)(pw + ol_);                                 \
        __half2 q0 = __hmul2(__hmul2(*(__half2*)&B4.x, *(__half2*)&W4.x), *(__half2*)&A4.x); \
        __half2 q1 = __hmul2(__hmul2(*(__half2*)&B4.y, *(__half2*)&W4.y), *(__half2*)&A4.y); \
        __half2 q2 = __hmul2(__hmul2(*(__half2*)&B4.z, *(__half2*)&W4.z), *(__half2*)&A4.z); \
        __half2 q3 = __hmul2(__hmul2(*(__half2*)&B4.w, *(__half2*)&W4.w), *(__half2*)&A4.w); \
        float2 s0 = __half22float2(q0);                                       \
        float2 s1 = __half22float2(q1);                                       \
        float2 s2 = __half22float2(q2);                                       \
        float2 s3 = __half22float2(q3);                                       \
        ax0 = fmaf(s0.x, (CGV), ax0);  ay0 = fmaf(s0.y, (CGV), ay0);          \
        ax1 = fmaf(s1.x, (CGV), ax1);  ay1 = fmaf(s1.y, (CGV), ay1);          \
        ax2 = fmaf(s2.x, (CGV), ax2);  ay2 = fmaf(s2.y, (CGV), ay2);          \
        ax3 = fmaf(s3.x, (CGV), ax3);  ay3 = fmaf(s3.y, (CGV), ay3);          \
    } while (0)

    #pragma unroll 2
    for (int q = 0; q < EPW_ / 4; ++q) {
        uint4  u0 = tp[2*q];
        uint4  u1 = tp[2*q + 1];
        float4 c4 = tc[q];
        STEP(u0.x, u0.y, c4.x);
        STEP(u0.z, u0.w, c4.y);
        STEP(u1.x, u1.y, c4.z);
        STEP(u1.z, u1.w, c4.w);
    }
    // final segment may straddle next warp's slice -> atomic, all batches
    {
        float* d0 = (float*)(ob + cur);
        float* d1 = (float*)(ob + cur + OBSZ);
        float* d2 = (float*)(ob + cur + 2*OBSZ);
        float* d3 = (float*)(ob + cur + 3*OBSZ);
        atomicAdd(d0, ax0); atomicAdd(d0 + 1, ay0);
        atomicAdd(d1, ax1); atomicAdd(d1 + 1, ay1);
        atomicAdd(d2, ax2); atomicAdd(d2 + 1, ay2);
        atomicAdd(d3, ax3); atomicAdd(d3 + 1, ay3);
    }
}

extern "C" void kernel_launch(void* const* d_in, const int* in_sizes, int n_in,
                              void* d_out, int out_size)
{
    const float* x1  = (const float*)d_in[0];
    const float* x2  = (const float*)d_in[1];
    const float* wgt = (const float*)d_in[2];
    const float* cg  = (const float*)d_in[3];
    const int*   Mo  = (const int*)d_in[4];
    const int*   M1  = (const int*)d_in[5];
    const int*   M2  = (const int*)d_in[6];
    const int*   Li  = (const int*)d_in[7];
    float* out = (float*)d_out;

    prep_kernel<<<1, 1024>>>(cg, Mo, M1, M2, Li);
    cudaFuncSetAttribute(wtp_kernel, cudaFuncAttributeMaxDynamicSharedMemorySize, SM_BYTES);
    wtp_kernel<<<GRID, THR, SM_BYTES>>>(x1, x2, wgt, out);
}